// round 1
// baseline (speedup 1.0000x reference)
#include <cuda_runtime.h>

// Problem dims
#define Bn   256
#define Sn   512
#define Cn   256
#define Vn   32
#define NLn  7
#define Mn   (Bn*Sn)          // 131072 tokens
#define EPSn 1e-5f

// GEMM tiling
#define BM 128
#define BN 128
#define BK 16

// Scratch (device globals are the sanctioned scratch mechanism)
__device__ float g_h[(size_t)Mn*Cn];    // residual stream
__device__ float g_a[(size_t)Mn*Cn];    // post-LN activation
__device__ float g_t[(size_t)Mn*Cn];    // GEMM output / E
__device__ float g_g[(size_t)Mn*Cn];    // G (gate pre-sigmoid)
__device__ float g_lat[Bn*Cn];          // z @ latent_W + b

// ---------------------------------------------------------------------------
// lat[b,c] = sum_k z[b,k] * latW[k,c] + latb[c]
__global__ __launch_bounds__(256) void latent_kernel(
    const float* __restrict__ z, const float* __restrict__ W,
    const float* __restrict__ bias)
{
    __shared__ float zs[Cn];
    int b = blockIdx.x, c = threadIdx.x;
    zs[c] = z[b*Cn + c];
    __syncthreads();
    float acc = bias[c];
    #pragma unroll 4
    for (int k = 0; k < Cn; k++) acc += zs[k] * W[k*Cn + c];
    g_lat[b*Cn + c] = acc;
}

// h[m,c] = emb[x[m],c] + lat[b,c]   (4 rows per block, float4 per thread)
__global__ __launch_bounds__(256) void embed_kernel(
    const int* __restrict__ x, const float* __restrict__ emb)
{
    int m = blockIdx.x*4 + (threadIdx.x >> 6);
    int t = threadIdx.x & 63;
    int b = m >> 9;
    int tok = x[m];
    float4 e = ((const float4*)(emb + (size_t)tok*Cn))[t];
    float4 l = ((const float4*)(g_lat + (size_t)b*Cn))[t];
    e.x += l.x; e.y += l.y; e.z += l.z; e.w += l.w;
    ((float4*)(g_h + (size_t)m*Cn))[t] = e;
}

// ---------------------------------------------------------------------------
// out[m,:] = lrelu(layernorm(in[m,:]) * gamma + beta), one warp per row
__global__ __launch_bounds__(256) void ln_act_kernel(
    const float* __restrict__ in, float* __restrict__ out,
    const float* __restrict__ gamma, const float* __restrict__ beta)
{
    int warp = threadIdx.x >> 5, lane = threadIdx.x & 31;
    int m = blockIdx.x*8 + warp;
    const float4* ir = (const float4*)(in + (size_t)m*Cn);
    float4 v0 = ir[lane];
    float4 v1 = ir[lane + 32];
    float s = v0.x+v0.y+v0.z+v0.w + v1.x+v1.y+v1.z+v1.w;
    float q = v0.x*v0.x+v0.y*v0.y+v0.z*v0.z+v0.w*v0.w
            + v1.x*v1.x+v1.y*v1.y+v1.z*v1.z+v1.w*v1.w;
    #pragma unroll
    for (int o = 16; o; o >>= 1) {
        s += __shfl_xor_sync(0xffffffffu, s, o);
        q += __shfl_xor_sync(0xffffffffu, q, o);
    }
    float mu = s * (1.0f/Cn);
    float var = q * (1.0f/Cn) - mu*mu;
    float rs = rsqrtf(var + EPSn);
    int c0 = lane*4, c1 = 128 + lane*4;
    float4 ga = *(const float4*)(gamma + c0);
    float4 gb = *(const float4*)(gamma + c1);
    float4 ba = *(const float4*)(beta  + c0);
    float4 bb = *(const float4*)(beta  + c1);
    float4 o0, o1;
    #define LNA(xv, gg, bbv) ({ float y = (xv - mu)*rs*gg + bbv; y >= 0.f ? y : 0.01f*y; })
    o0.x = LNA(v0.x, ga.x, ba.x); o0.y = LNA(v0.y, ga.y, ba.y);
    o0.z = LNA(v0.z, ga.z, ba.z); o0.w = LNA(v0.w, ga.w, ba.w);
    o1.x = LNA(v1.x, gb.x, bb.x); o1.y = LNA(v1.y, gb.y, bb.y);
    o1.z = LNA(v1.z, gb.z, bb.z); o1.w = LNA(v1.w, gb.w, bb.w);
    #undef LNA
    float4* orow = (float4*)(out + (size_t)m*Cn);
    orow[lane]      = o0;
    orow[lane + 32] = o1;
}

// ---------------------------------------------------------------------------
// out = A @ W + bias  (M x 256 @ 256 x 256), 128x128x16 tiles, 8x8 micro
__global__ __launch_bounds__(256) void gemm_bias_kernel(
    const float* __restrict__ A, const float* __restrict__ W,
    const float* __restrict__ bias, float* __restrict__ out)
{
    __shared__ float As[BK][BM+4];
    __shared__ float Bs[BK][BN];
    int tid = threadIdx.x;
    int tx = tid & 15, ty = tid >> 4;
    int row0 = blockIdx.x * BM;
    int col0 = blockIdx.y * BN;

    float acc[8][8];
    #pragma unroll
    for (int i = 0; i < 8; i++)
        #pragma unroll
        for (int j = 0; j < 8; j++) acc[i][j] = 0.f;

    int a_row = tid >> 2;            // 0..63
    int a_k4  = (tid & 3) * 4;       // 0,4,8,12
    int b_k   = tid >> 5;            // 0..7
    int b_n   = (tid & 31) * 4;      // 0..124

    for (int kt = 0; kt < Cn; kt += BK) {
        #pragma unroll
        for (int hh = 0; hh < 2; hh++) {
            int r = a_row + hh*64;
            float4 v = *(const float4*)(A + (size_t)(row0 + r)*Cn + kt + a_k4);
            As[a_k4+0][r] = v.x; As[a_k4+1][r] = v.y;
            As[a_k4+2][r] = v.z; As[a_k4+3][r] = v.w;
        }
        #pragma unroll
        for (int hh = 0; hh < 2; hh++) {
            int k = b_k + hh*8;
            *(float4*)(&Bs[k][b_n]) = *(const float4*)(W + (size_t)(kt+k)*Cn + col0 + b_n);
        }
        __syncthreads();
        #pragma unroll
        for (int kk = 0; kk < BK; kk++) {
            float4 a0 = *(const float4*)(&As[kk][ty*8]);
            float4 a1 = *(const float4*)(&As[kk][ty*8+4]);
            float4 bqa = *(const float4*)(&Bs[kk][tx*8]);
            float4 bqb = *(const float4*)(&Bs[kk][tx*8+4]);
            float ar[8] = {a0.x,a0.y,a0.z,a0.w,a1.x,a1.y,a1.z,a1.w};
            float br[8] = {bqa.x,bqa.y,bqa.z,bqa.w,bqb.x,bqb.y,bqb.z,bqb.w};
            #pragma unroll
            for (int i = 0; i < 8; i++)
                #pragma unroll
                for (int j = 0; j < 8; j++)
                    acc[i][j] += ar[i]*br[j];
        }
        __syncthreads();
    }
    #pragma unroll
    for (int i = 0; i < 8; i++) {
        size_t r = (size_t)row0 + ty*8 + i;
        #pragma unroll
        for (int j = 0; j < 8; j += 4) {
            int c = col0 + tx*8 + j;
            float4 o;
            o.x = acc[i][j]   + bias[c];
            o.y = acc[i][j+1] + bias[c+1];
            o.z = acc[i][j+2] + bias[c+2];
            o.w = acc[i][j+3] + bias[c+3];
            *(float4*)(out + r*Cn + c) = o;
        }
    }
}

// out = shift_d(A) @ W0 + A @ W1 + bias   (causal dilated conv, kernel=2)
__global__ __launch_bounds__(256) void gemm_conv_kernel(
    const float* __restrict__ A, const float* __restrict__ W0,
    const float* __restrict__ W1, const float* __restrict__ bias,
    float* __restrict__ out, int d)
{
    __shared__ float As0[BK][BM+4];
    __shared__ float As1[BK][BM+4];
    __shared__ float Bs0[BK][BN];
    __shared__ float Bs1[BK][BN];
    int tid = threadIdx.x;
    int tx = tid & 15, ty = tid >> 4;
    int row0 = blockIdx.x * BM;
    int col0 = blockIdx.y * BN;

    float acc[8][8];
    #pragma unroll
    for (int i = 0; i < 8; i++)
        #pragma unroll
        for (int j = 0; j < 8; j++) acc[i][j] = 0.f;

    int a_row = tid >> 2;
    int a_k4  = (tid & 3) * 4;
    int b_k   = tid >> 5;
    int b_n   = (tid & 31) * 4;

    for (int kt = 0; kt < Cn; kt += BK) {
        #pragma unroll
        for (int hh = 0; hh < 2; hh++) {
            int r = a_row + hh*64;
            int rg = row0 + r;
            float4 v1 = *(const float4*)(A + (size_t)rg*Cn + kt + a_k4);
            As1[a_k4+0][r] = v1.x; As1[a_k4+1][r] = v1.y;
            As1[a_k4+2][r] = v1.z; As1[a_k4+3][r] = v1.w;
            int s = rg & (Sn-1);
            float4 v0 = make_float4(0.f,0.f,0.f,0.f);
            if (s >= d)
                v0 = *(const float4*)(A + (size_t)(rg - d)*Cn + kt + a_k4);
            As0[a_k4+0][r] = v0.x; As0[a_k4+1][r] = v0.y;
            As0[a_k4+2][r] = v0.z; As0[a_k4+3][r] = v0.w;
        }
        #pragma unroll
        for (int hh = 0; hh < 2; hh++) {
            int k = b_k + hh*8;
            *(float4*)(&Bs0[k][b_n]) = *(const float4*)(W0 + (size_t)(kt+k)*Cn + col0 + b_n);
            *(float4*)(&Bs1[k][b_n]) = *(const float4*)(W1 + (size_t)(kt+k)*Cn + col0 + b_n);
        }
        __syncthreads();
        #pragma unroll
        for (int kk = 0; kk < BK; kk++) {
            float4 p, q;
            p = *(const float4*)(&As0[kk][ty*8]);   q = *(const float4*)(&As0[kk][ty*8+4]);
            float a0r[8] = {p.x,p.y,p.z,p.w,q.x,q.y,q.z,q.w};
            p = *(const float4*)(&As1[kk][ty*8]);   q = *(const float4*)(&As1[kk][ty*8+4]);
            float a1r[8] = {p.x,p.y,p.z,p.w,q.x,q.y,q.z,q.w};
            p = *(const float4*)(&Bs0[kk][tx*8]);   q = *(const float4*)(&Bs0[kk][tx*8+4]);
            float b0r[8] = {p.x,p.y,p.z,p.w,q.x,q.y,q.z,q.w};
            p = *(const float4*)(&Bs1[kk][tx*8]);   q = *(const float4*)(&Bs1[kk][tx*8+4]);
            float b1r[8] = {p.x,p.y,p.z,p.w,q.x,q.y,q.z,q.w};
            #pragma unroll
            for (int i = 0; i < 8; i++)
                #pragma unroll
                for (int j = 0; j < 8; j++)
                    acc[i][j] += a0r[i]*b0r[j] + a1r[i]*b1r[j];
        }
        __syncthreads();
    }
    #pragma unroll
    for (int i = 0; i < 8; i++) {
        size_t r = (size_t)row0 + ty*8 + i;
        #pragma unroll
        for (int j = 0; j < 8; j += 4) {
            int c = col0 + tx*8 + j;
            float4 o;
            o.x = acc[i][j]   + bias[c];
            o.y = acc[i][j+1] + bias[c+1];
            o.z = acc[i][j+2] + bias[c+2];
            o.w = acc[i][j+3] + bias[c+3];
            *(float4*)(out + r*Cn + c) = o;
        }
    }
}

// h += E * sigmoid(G)
__global__ __launch_bounds__(256) void gate_res_kernel()
{
    size_t i = (size_t)blockIdx.x * blockDim.x + threadIdx.x;
    float4 e = ((const float4*)g_t)[i];
    float4 g = ((const float4*)g_g)[i];
    float4 h = ((float4*)g_h)[i];
    h.x += e.x * (1.f/(1.f + __expf(-g.x)));
    h.y += e.y * (1.f/(1.f + __expf(-g.y)));
    h.z += e.z * (1.f/(1.f + __expf(-g.z)));
    h.w += e.w * (1.f/(1.f + __expf(-g.w)));
    ((float4*)g_h)[i] = h;
}

// ---------------------------------------------------------------------------
// head: logits = h @ out_W + out_b; log_softmax over V=32; gather x[:,1:]
// one warp per token (lane = vocab id), 8 tokens per block
__global__ __launch_bounds__(256) void head_kernel(
    const int* __restrict__ x, const float* __restrict__ outW,
    const float* __restrict__ outb, float* __restrict__ out)
{
    __shared__ float Ws[Cn][Vn+1];
    __shared__ float hs[8][Cn];
    int tid = threadIdx.x;
    for (int i = tid; i < Cn*Vn; i += 256)
        Ws[i >> 5][i & 31] = outW[i];
    int warp = tid >> 5, lane = tid & 31;
    int m = blockIdx.x*8 + warp;
    const float4* hr = (const float4*)(g_h + (size_t)m*Cn);
    ((float4*)hs[warp])[lane]      = hr[lane];
    ((float4*)hs[warp])[lane + 32] = hr[lane + 32];
    __syncthreads();
    float acc = outb[lane];
    #pragma unroll 8
    for (int k = 0; k < Cn; k++)
        acc += hs[warp][k] * Ws[k][lane];
    float mx = acc;
    #pragma unroll
    for (int o = 16; o; o >>= 1) mx = fmaxf(mx, __shfl_xor_sync(0xffffffffu, mx, o));
    float ex = expf(acc - mx), sum = ex;
    #pragma unroll
    for (int o = 16; o; o >>= 1) sum += __shfl_xor_sync(0xffffffffu, sum, o);
    float lse = mx + logf(sum);
    int b = m >> 9, s = m & (Sn-1);
    if (s < Sn-1) {
        int tgt = x[m + 1];
        float lt = __shfl_sync(0xffffffffu, acc, tgt);
        if (lane == 0) out[(size_t)b*(Sn-1) + s] = lt - lse;
    }
}

// ---------------------------------------------------------------------------
extern "C" void kernel_launch(void* const* d_in, const int* in_sizes, int n_in,
                              void* d_out, int out_size)
{
    const int*   x    = (const int*)  d_in[0];
    const float* z    = (const float*)d_in[1];
    const float* emb  = (const float*)d_in[2];
    const float* latW = (const float*)d_in[3];
    const float* latb = (const float*)d_in[4];
    const float* ln1g = (const float*)d_in[5];
    const float* ln1b = (const float*)d_in[6];
    const float* w1   = (const float*)d_in[7];
    const float* b1   = (const float*)d_in[8];
    const float* ln2g = (const float*)d_in[9];
    const float* ln2b = (const float*)d_in[10];
    const float* wd   = (const float*)d_in[11];
    const float* bd   = (const float*)d_in[12];
    const float* ln3g = (const float*)d_in[13];
    const float* ln3b = (const float*)d_in[14];
    const float* we   = (const float*)d_in[15];
    const float* be   = (const float*)d_in[16];
    const float* wg   = (const float*)d_in[17];
    const float* bg   = (const float*)d_in[18];
    const float* outW = (const float*)d_in[19];
    const float* outb = (const float*)d_in[20];

    float *hP, *aP, *tP, *gP;
    cudaGetSymbolAddress((void**)&hP, g_h);
    cudaGetSymbolAddress((void**)&aP, g_a);
    cudaGetSymbolAddress((void**)&tP, g_t);
    cudaGetSymbolAddress((void**)&gP, g_g);

    latent_kernel<<<Bn, Cn>>>(z, latW, latb);
    embed_kernel<<<Mn/4, 256>>>(x, emb);

    dim3 ggrid(Mn/BM, Cn/BN);
    const size_t CC = (size_t)Cn*Cn;

    for (int i = 0; i < NLn; i++) {
        int d = 1 << i;
        // t = lrelu(ln1(h))
        ln_act_kernel<<<Mn/8, 256>>>(hP, aP, ln1g + i*Cn, ln1b + i*Cn);
        // t = a @ w1 + b1
        gemm_bias_kernel<<<ggrid, 256>>>(aP, w1 + i*CC, b1 + i*Cn, tP);
        // a = lrelu(ln2(t))
        ln_act_kernel<<<Mn/8, 256>>>(tP, aP, ln2g + i*Cn, ln2b + i*Cn);
        // t = shift(a,d) @ wd0 + a @ wd1 + bd
        gemm_conv_kernel<<<ggrid, 256>>>(aP, wd + (size_t)i*2*CC,
                                         wd + (size_t)i*2*CC + CC,
                                         bd + i*Cn, tP, d);
        // a = lrelu(ln3(t))
        ln_act_kernel<<<Mn/8, 256>>>(tP, aP, ln3g + i*Cn, ln3b + i*Cn);
        // E = a @ we + be ; G = a @ wg + bg
        gemm_bias_kernel<<<ggrid, 256>>>(aP, we + i*CC, be + i*Cn, tP);
        gemm_bias_kernel<<<ggrid, 256>>>(aP, wg + i*CC, bg + i*Cn, gP);
        // h += E * sigmoid(G)
        gate_res_kernel<<<(Mn*(Cn/4))/256, 256>>>();
    }

    head_kernel<<<Mn/8, 256>>>(x, outW, outb, (float*)d_out);
}

// round 3
// speedup vs baseline: 2.0461x; 2.0461x over previous
#include <cuda_runtime.h>
#include <cstdint>

// Problem dims
#define Bn   256
#define Sn   512
#define Cn   256
#define Vn   32
#define NLn  7
#define Mn   (Bn*Sn)          // 131072 tokens
#define EPSn 1e-5f

// GEMM tiling
#define BM 128
#define BN 128
#define BK 32
#define LDS_PITCH 132         // BM + 4 pad

// Scratch
__device__ float g_h[(size_t)Mn*Cn];    // residual stream
__device__ float g_a[(size_t)Mn*Cn];    // post-LN activation
__device__ float g_t[(size_t)Mn*Cn];    // GEMM output / E
__device__ float g_g[(size_t)Mn*Cn];    // G (gate pre-sigmoid)
__device__ float g_lat[Bn*Cn];          // z @ latent_W + b
__device__ float g_wt[35*65536];        // transposed weights [35][N=256][K=256]

// ---------------------------------------------------------------------------
__device__ __forceinline__ uint32_t f2tf32(float x) {
    uint32_t y;
    asm("cvt.rna.tf32.f32 %0, %1;" : "=r"(y) : "f"(x));
    return y;
}

__device__ __forceinline__ void mma_tf32(float* c, const uint32_t* a, const uint32_t* b) {
    asm volatile(
        "mma.sync.aligned.m16n8k8.row.col.f32.tf32.tf32.f32 "
        "{%0,%1,%2,%3}, {%4,%5,%6,%7}, {%8,%9}, {%0,%1,%2,%3};"
        : "+f"(c[0]), "+f"(c[1]), "+f"(c[2]), "+f"(c[3])
        : "r"(a[0]), "r"(a[1]), "r"(a[2]), "r"(a[3]), "r"(b[0]), "r"(b[1]));
}

// ---------------------------------------------------------------------------
// Weight transpose: g_wt[mat][n][k] = W[k][n]; 35 matrices of 256x256
__global__ __launch_bounds__(256) void transpose_w_kernel(
    const float* __restrict__ w1, const float* __restrict__ wd,
    const float* __restrict__ we, const float* __restrict__ wg)
{
    __shared__ float t[32][33];
    int mat = blockIdx.z;
    int layer = mat / 5, wh = mat % 5;
    const size_t CC = 65536;
    const float* src;
    if      (wh == 0) src = w1 + (size_t)layer*CC;
    else if (wh == 1) src = wd + (size_t)layer*2*CC;
    else if (wh == 2) src = wd + (size_t)layer*2*CC + CC;
    else if (wh == 3) src = we + (size_t)layer*CC;
    else              src = wg + (size_t)layer*CC;
    int tx = threadIdx.x & 31, ty = threadIdx.x >> 5;
    int k0 = blockIdx.x*32, n0 = blockIdx.y*32;
    #pragma unroll
    for (int j = 0; j < 32; j += 8)
        t[ty+j][tx] = src[(size_t)(k0+ty+j)*256 + n0 + tx];
    __syncthreads();
    float* dst = g_wt + (size_t)mat*CC;
    #pragma unroll
    for (int j = 0; j < 32; j += 8)
        dst[(size_t)(n0+ty+j)*256 + k0 + tx] = t[tx][ty+j];
}

// ---------------------------------------------------------------------------
// tf32 mma.sync GEMM: out[128,128 tile] = sum_taps shift(A) @ Wt^T + bias
// A: [M,256] fp32 row-major.  Wt: [256,256], row n holds K contiguous (B col-major).
// Smem: As[k][m], Bs[k][n], tf32-converted. 8 warps = 2x4, warp tile 64x32.
template<int TAPS>
__global__ __launch_bounds__(256) void gemm_mma_kernel(
    const float* __restrict__ A,
    const float* __restrict__ W0t, const float* __restrict__ W1t,
    const float* __restrict__ bias, float* __restrict__ out, int d)
{
    extern __shared__ uint32_t smem[];
    // per tap: As (BK*LDS_PITCH) then Bs (BK*LDS_PITCH)
    const int TAPSZ = 2 * BK * LDS_PITCH;

    int tid = threadIdx.x;
    int wid = tid >> 5, lane = tid & 31;
    int g = lane >> 2, tq = lane & 3;
    int warp_m = wid >> 2, warp_n = wid & 3;
    int m_base = warp_m * 64, n_base = warp_n * 32;
    int row0 = blockIdx.x * BM, n0 = blockIdx.y * BN;

    float acc[4][4][4];
    #pragma unroll
    for (int i = 0; i < 4; i++)
        #pragma unroll
        for (int j = 0; j < 4; j++)
            #pragma unroll
            for (int q = 0; q < 4; q++) acc[i][j][q] = 0.f;

    for (int kt = 0; kt < Cn; kt += BK) {
        // ---- stage tiles (transpose to [k][m] / [k][n], convert tf32)
        #pragma unroll
        for (int tap = 0; tap < TAPS; tap++) {
            int shift = (TAPS == 2 && tap == 0) ? d : 0;
            const float* W = tap ? W1t : W0t;
            uint32_t* As = smem + tap * TAPSZ;
            uint32_t* Bs = As + BK * LDS_PITCH;
            #pragma unroll
            for (int i = 0; i < 4; i++) {
                int idx = tid + 256*i;          // 0..1023
                int row = idx >> 3;             // 0..127
                int k4  = (idx & 7) * 4;        // 0..28
                // A
                int gm = row0 + row;
                float4 v = make_float4(0.f, 0.f, 0.f, 0.f);
                if (shift == 0 || (gm & (Sn-1)) >= shift)
                    v = *(const float4*)(A + (size_t)(gm - shift)*Cn + kt + k4);
                As[(k4+0)*LDS_PITCH + row] = f2tf32(v.x);
                As[(k4+1)*LDS_PITCH + row] = f2tf32(v.y);
                As[(k4+2)*LDS_PITCH + row] = f2tf32(v.z);
                As[(k4+3)*LDS_PITCH + row] = f2tf32(v.w);
                // B
                float4 w = *(const float4*)(W + (size_t)(n0 + row)*Cn + kt + k4);
                Bs[(k4+0)*LDS_PITCH + row] = f2tf32(w.x);
                Bs[(k4+1)*LDS_PITCH + row] = f2tf32(w.y);
                Bs[(k4+2)*LDS_PITCH + row] = f2tf32(w.z);
                Bs[(k4+3)*LDS_PITCH + row] = f2tf32(w.w);
            }
        }
        __syncthreads();
        // ---- compute
        #pragma unroll
        for (int tap = 0; tap < TAPS; tap++) {
            const uint32_t* As = smem + tap * TAPSZ;
            const uint32_t* Bs = As + BK * LDS_PITCH;
            #pragma unroll
            for (int ks = 0; ks < BK; ks += 8) {
                uint32_t afr[4][4];
                #pragma unroll
                for (int mi = 0; mi < 4; mi++) {
                    int m = m_base + mi*16 + g;
                    afr[mi][0] = As[(ks+tq)  *LDS_PITCH + m];
                    afr[mi][1] = As[(ks+tq)  *LDS_PITCH + m + 8];
                    afr[mi][2] = As[(ks+tq+4)*LDS_PITCH + m];
                    afr[mi][3] = As[(ks+tq+4)*LDS_PITCH + m + 8];
                }
                uint32_t bfr[4][2];
                #pragma unroll
                for (int ni = 0; ni < 4; ni++) {
                    int n = n_base + ni*8 + g;
                    bfr[ni][0] = Bs[(ks+tq)  *LDS_PITCH + n];
                    bfr[ni][1] = Bs[(ks+tq+4)*LDS_PITCH + n];
                }
                #pragma unroll
                for (int mi = 0; mi < 4; mi++)
                    #pragma unroll
                    for (int ni = 0; ni < 4; ni++)
                        mma_tf32(acc[mi][ni], afr[mi], bfr[ni]);
            }
        }
        __syncthreads();
    }

    // ---- epilogue: add bias, store
    #pragma unroll
    for (int mi = 0; mi < 4; mi++) {
        int r0g = row0 + m_base + mi*16 + g;
        #pragma unroll
        for (int ni = 0; ni < 4; ni++) {
            int c = n0 + n_base + ni*8 + tq*2;
            float bx = bias[c], by = bias[c+1];
            float2 o0 = make_float2(acc[mi][ni][0] + bx, acc[mi][ni][1] + by);
            float2 o1 = make_float2(acc[mi][ni][2] + bx, acc[mi][ni][3] + by);
            *(float2*)(out + (size_t)r0g*Cn + c)     = o0;
            *(float2*)(out + (size_t)(r0g+8)*Cn + c) = o1;
        }
    }
}

// ---------------------------------------------------------------------------
__global__ __launch_bounds__(256) void latent_kernel(
    const float* __restrict__ z, const float* __restrict__ W,
    const float* __restrict__ bias)
{
    __shared__ float zs[Cn];
    int b = blockIdx.x, c = threadIdx.x;
    zs[c] = z[b*Cn + c];
    __syncthreads();
    float acc = bias[c];
    #pragma unroll 4
    for (int k = 0; k < Cn; k++) acc += zs[k] * W[k*Cn + c];
    g_lat[b*Cn + c] = acc;
}

__global__ __launch_bounds__(256) void embed_kernel(
    const int* __restrict__ x, const float* __restrict__ emb)
{
    int m = blockIdx.x*4 + (threadIdx.x >> 6);
    int t = threadIdx.x & 63;
    int b = m >> 9;
    int tok = x[m];
    float4 e = ((const float4*)(emb + (size_t)tok*Cn))[t];
    float4 l = ((const float4*)(g_lat + (size_t)b*Cn))[t];
    e.x += l.x; e.y += l.y; e.z += l.z; e.w += l.w;
    ((float4*)(g_h + (size_t)m*Cn))[t] = e;
}

__global__ __launch_bounds__(256) void ln_act_kernel(
    const float* __restrict__ in, float* __restrict__ out,
    const float* __restrict__ gamma, const float* __restrict__ beta)
{
    int warp = threadIdx.x >> 5, lane = threadIdx.x & 31;
    int m = blockIdx.x*8 + warp;
    const float4* ir = (const float4*)(in + (size_t)m*Cn);
    float4 v0 = ir[lane];
    float4 v1 = ir[lane + 32];
    float s = v0.x+v0.y+v0.z+v0.w + v1.x+v1.y+v1.z+v1.w;
    float q = v0.x*v0.x+v0.y*v0.y+v0.z*v0.z+v0.w*v0.w
            + v1.x*v1.x+v1.y*v1.y+v1.z*v1.z+v1.w*v1.w;
    #pragma unroll
    for (int o = 16; o; o >>= 1) {
        s += __shfl_xor_sync(0xffffffffu, s, o);
        q += __shfl_xor_sync(0xffffffffu, q, o);
    }
    float mu = s * (1.0f/Cn);
    float var = q * (1.0f/Cn) - mu*mu;
    float rs = rsqrtf(var + EPSn);
    int c0 = lane*4, c1 = 128 + lane*4;
    float4 ga = *(const float4*)(gamma + c0);
    float4 gb = *(const float4*)(gamma + c1);
    float4 ba = *(const float4*)(beta  + c0);
    float4 bb = *(const float4*)(beta  + c1);
    float4 o0, o1;
    #define LNA(xv, gg, bbv) ({ float y = (xv - mu)*rs*gg + bbv; y >= 0.f ? y : 0.01f*y; })
    o0.x = LNA(v0.x, ga.x, ba.x); o0.y = LNA(v0.y, ga.y, ba.y);
    o0.z = LNA(v0.z, ga.z, ba.z); o0.w = LNA(v0.w, ga.w, ba.w);
    o1.x = LNA(v1.x, gb.x, bb.x); o1.y = LNA(v1.y, gb.y, bb.y);
    o1.z = LNA(v1.z, gb.z, bb.z); o1.w = LNA(v1.w, gb.w, bb.w);
    #undef LNA
    float4* orow = (float4*)(out + (size_t)m*Cn);
    orow[lane]      = o0;
    orow[lane + 32] = o1;
}

__global__ __launch_bounds__(256) void gate_res_kernel()
{
    size_t i = (size_t)blockIdx.x * blockDim.x + threadIdx.x;
    float4 e = ((const float4*)g_t)[i];
    float4 g = ((const float4*)g_g)[i];
    float4 h = ((float4*)g_h)[i];
    h.x += e.x * (1.f/(1.f + __expf(-g.x)));
    h.y += e.y * (1.f/(1.f + __expf(-g.y)));
    h.z += e.z * (1.f/(1.f + __expf(-g.z)));
    h.w += e.w * (1.f/(1.f + __expf(-g.w)));
    ((float4*)g_h)[i] = h;
}

__global__ __launch_bounds__(256) void head_kernel(
    const int* __restrict__ x, const float* __restrict__ outW,
    const float* __restrict__ outb, float* __restrict__ out)
{
    __shared__ float Ws[Cn][Vn+1];
    __shared__ float hs[8][Cn];
    int tid = threadIdx.x;
    for (int i = tid; i < Cn*Vn; i += 256)
        Ws[i >> 5][i & 31] = outW[i];
    int warp = tid >> 5, lane = tid & 31;
    int m = blockIdx.x*8 + warp;
    const float4* hr = (const float4*)(g_h + (size_t)m*Cn);
    ((float4*)hs[warp])[lane]      = hr[lane];
    ((float4*)hs[warp])[lane + 32] = hr[lane + 32];
    __syncthreads();
    float acc = outb[lane];
    #pragma unroll 8
    for (int k = 0; k < Cn; k++)
        acc += hs[warp][k] * Ws[k][lane];
    float mx = acc;
    #pragma unroll
    for (int o = 16; o; o >>= 1) mx = fmaxf(mx, __shfl_xor_sync(0xffffffffu, mx, o));
    float ex = expf(acc - mx), sum = ex;
    #pragma unroll
    for (int o = 16; o; o >>= 1) sum += __shfl_xor_sync(0xffffffffu, sum, o);
    float lse = mx + logf(sum);
    int b = m >> 9, s = m & (Sn-1);
    if (s < Sn-1) {
        int tgt = x[m + 1];
        float lt = __shfl_sync(0xffffffffu, acc, tgt);
        if (lane == 0) out[(size_t)b*(Sn-1) + s] = lt - lse;
    }
}

// ---------------------------------------------------------------------------
extern "C" void kernel_launch(void* const* d_in, const int* in_sizes, int n_in,
                              void* d_out, int out_size)
{
    const int*   x    = (const int*)  d_in[0];
    const float* z    = (const float*)d_in[1];
    const float* emb  = (const float*)d_in[2];
    const float* latW = (const float*)d_in[3];
    const float* latb = (const float*)d_in[4];
    const float* ln1g = (const float*)d_in[5];
    const float* ln1b = (const float*)d_in[6];
    const float* w1   = (const float*)d_in[7];
    const float* b1   = (const float*)d_in[8];
    const float* ln2g = (const float*)d_in[9];
    const float* ln2b = (const float*)d_in[10];
    const float* wd   = (const float*)d_in[11];
    const float* bd   = (const float*)d_in[12];
    const float* ln3g = (const float*)d_in[13];
    const float* ln3b = (const float*)d_in[14];
    const float* we   = (const float*)d_in[15];
    const float* be   = (const float*)d_in[16];
    const float* wg   = (const float*)d_in[17];
    const float* bg   = (const float*)d_in[18];
    const float* outW = (const float*)d_in[19];
    const float* outb = (const float*)d_in[20];

    float *hP, *aP, *tP, *gP, *wtP;
    cudaGetSymbolAddress((void**)&hP, g_h);
    cudaGetSymbolAddress((void**)&aP, g_a);
    cudaGetSymbolAddress((void**)&tP, g_t);
    cudaGetSymbolAddress((void**)&gP, g_g);
    cudaGetSymbolAddress((void**)&wtP, g_wt);

    const int SMEM1 = 2 * BK * LDS_PITCH * 4;   // 33792
    const int SMEM2 = 4 * BK * LDS_PITCH * 4;   // 67584
    cudaFuncSetAttribute(gemm_mma_kernel<1>, cudaFuncAttributeMaxDynamicSharedMemorySize, SMEM1);
    cudaFuncSetAttribute(gemm_mma_kernel<2>, cudaFuncAttributeMaxDynamicSharedMemorySize, SMEM2);

    dim3 tgrid(8, 8, 35);
    transpose_w_kernel<<<tgrid, 256>>>(w1, wd, we, wg);
    latent_kernel<<<Bn, Cn>>>(z, latW, latb);
    embed_kernel<<<Mn/4, 256>>>(x, emb);

    dim3 ggrid(Mn/BM, Cn/BN);
    const size_t CC = (size_t)Cn*Cn;

    for (int i = 0; i < NLn; i++) {
        int d = 1 << i;
        // a = lrelu(ln1(h))
        ln_act_kernel<<<Mn/8, 256>>>(hP, aP, ln1g + i*Cn, ln1b + i*Cn);
        // t = a @ w1 + b1
        gemm_mma_kernel<1><<<ggrid, 256, SMEM1>>>(aP, wtP + (i*5+0)*CC, nullptr,
                                                  b1 + i*Cn, tP, 0);
        // a = lrelu(ln2(t))
        ln_act_kernel<<<Mn/8, 256>>>(tP, aP, ln2g + i*Cn, ln2b + i*Cn);
        // t = shift(a,d) @ wd0 + a @ wd1 + bd
        gemm_mma_kernel<2><<<ggrid, 256, SMEM2>>>(aP, wtP + (i*5+1)*CC, wtP + (i*5+2)*CC,
                                                  bd + i*Cn, tP, d);
        // a = lrelu(ln3(t))
        ln_act_kernel<<<Mn/8, 256>>>(tP, aP, ln3g + i*Cn, ln3b + i*Cn);
        // E = a @ we + be ; G = a @ wg + bg
        gemm_mma_kernel<1><<<ggrid, 256, SMEM1>>>(aP, wtP + (i*5+3)*CC, nullptr,
                                                  be + i*Cn, tP, 0);
        gemm_mma_kernel<1><<<ggrid, 256, SMEM1>>>(aP, wtP + (i*5+4)*CC, nullptr,
                                                  bg + i*Cn, gP, 0);
        // h += E * sigmoid(G)
        gate_res_kernel<<<(Mn*(Cn/4))/256, 256>>>();
    }

    head_kernel<<<Mn/8, 256>>>(x, outW, outb, (float*)d_out);
}

// round 5
// speedup vs baseline: 3.4618x; 1.6918x over previous
#include <cuda_runtime.h>
#include <cstdint>

// Problem dims
#define Bn   256
#define Sn   512
#define Cn   256
#define Vn   32
#define NLn  7
#define Mn   (Bn*Sn)
#define EPSn 1e-5f

// Scratch
__device__ float g_h[(size_t)Mn*Cn];
__device__ float g_a[(size_t)Mn*Cn];
__device__ float g_t[(size_t)Mn*Cn];
__device__ float g_lat[Bn*Cn];
__device__ float g_wt[35*65536];        // transposed weights [35][N=256][K=256]

// ---------------------------------------------------------------------------
__device__ __forceinline__ uint32_t smem_u32(const void* p) {
    uint32_t a;
    asm("{ .reg .u64 t; cvta.to.shared.u64 t, %1; cvt.u32.u64 %0, t; }"
        : "=r"(a) : "l"(p));
    return a;
}
__device__ __forceinline__ uint32_t lds32(uint32_t a) {
    uint32_t v;
    asm volatile("ld.shared.b32 %0, [%1];" : "=r"(v) : "r"(a));
    return v;
}
#define CP16(dst, src, sz) \
    asm volatile("cp.async.cg.shared.global [%0], [%1], 16, %2;" \
        :: "r"(dst), "l"(src), "r"(sz))
#define CPCOMMIT() asm volatile("cp.async.commit_group;")
#define CPWAIT(n)  asm volatile("cp.async.wait_group %0;" :: "n"(n))

__device__ __forceinline__ void mma_tf32(float* c, const uint32_t* a, const uint32_t* b) {
    asm volatile(
        "mma.sync.aligned.m16n8k8.row.col.f32.tf32.tf32.f32 "
        "{%0,%1,%2,%3}, {%4,%5,%6,%7}, {%8,%9}, {%0,%1,%2,%3};"
        : "+f"(c[0]), "+f"(c[1]), "+f"(c[2]), "+f"(c[3])
        : "r"(a[0]), "r"(a[1]), "r"(a[2]), "r"(a[3]), "r"(b[0]), "r"(b[1]));
}

// ---------------------------------------------------------------------------
// Weight transpose: g_wt[mat][n][k] = W[k][n]
__global__ __launch_bounds__(256) void transpose_w_kernel(
    const float* __restrict__ w1, const float* __restrict__ wd,
    const float* __restrict__ we, const float* __restrict__ wg)
{
    __shared__ float t[32][33];
    int mat = blockIdx.z;
    int layer = mat / 5, wh = mat % 5;
    const size_t CC = 65536;
    const float* src;
    if      (wh == 0) src = w1 + (size_t)layer*CC;
    else if (wh == 1) src = wd + (size_t)layer*2*CC;
    else if (wh == 2) src = wd + (size_t)layer*2*CC + CC;
    else if (wh == 3) src = we + (size_t)layer*CC;
    else              src = wg + (size_t)layer*CC;
    int tx = threadIdx.x & 31, ty = threadIdx.x >> 5;
    int k0 = blockIdx.x*32, n0 = blockIdx.y*32;
    #pragma unroll
    for (int j = 0; j < 32; j += 8)
        t[ty+j][tx] = src[(size_t)(k0+ty+j)*256 + n0 + tx];
    __syncthreads();
    float* dst = g_wt + (size_t)mat*CC;
    #pragma unroll
    for (int j = 0; j < 32; j += 8)
        dst[(size_t)(n0+ty+j)*256 + k0 + tx] = t[tx][ty+j];
}

// ---------------------------------------------------------------------------
// Tiled mma GEMM, cp.async double-buffered, SW128-swizzled smem [row][k] tiles.
// TAPS=1: out = A@W0^T + bias.  TAPS=2 (conv): out = shift_d(A)@W0^T + A@W1^T + bias.
// Tile 128x128x32, 8 warps (2x4), warp tile 64x32.
template<int TAPS>
__global__ __launch_bounds__(256) void gemm_cp_kernel(
    const float* __restrict__ A,
    const float* __restrict__ W0t, const float* __restrict__ W1t,
    const float* __restrict__ bias, float* __restrict__ out, int d)
{
    extern __shared__ char smem[];
    const uint32_t STAGE = TAPS * 32768u;     // per-stage bytes (TAPS A-tiles + TAPS B-tiles)
    uint32_t sb = smem_u32(smem);

    int tid = threadIdx.x;
    int wid = tid >> 5, lane = tid & 31;
    int g = lane >> 2, tq = lane & 3;
    int warp_m = wid >> 2, warp_n = wid & 3;
    int m_base = warp_m * 64, n_base = warp_n * 32;
    int row0 = blockIdx.x * 128, n0 = blockIdx.y * 128;

    // staging indices
    int sm_row = 0, sm_ch = 0;
    { int c0 = tid; sm_row = c0 >> 3; sm_ch = c0 & 7; }

    float acc[4][4][4];
    #pragma unroll
    for (int i = 0; i < 4; i++)
        #pragma unroll
        for (int j = 0; j < 4; j++)
            #pragma unroll
            for (int q = 0; q < 4; q++) acc[i][j][q] = 0.f;

    // fragment base offsets (relative, ks=0; chunk = g for all our rows)
    uint32_t aRel[4][2], bRel[4];
    #pragma unroll
    for (int mi = 0; mi < 4; mi++) {
        int m = m_base + mi*16 + g;
        aRel[mi][0] = (uint32_t)m*128 + (g<<4) + tq*4;
        aRel[mi][1] = (uint32_t)(m+8)*128 + (g<<4) + tq*4;
    }
    #pragma unroll
    for (int ni = 0; ni < 4; ni++) {
        int n = n_base + ni*8 + g;
        bRel[ni] = (uint32_t)n*128 + (g<<4) + tq*4;
    }

    // ---- stage loader
    auto stage = [&](int buf, int kt) {
        uint32_t base = sb + buf*STAGE;
        #pragma unroll
        for (int tap = 0; tap < TAPS; tap++) {
            int shift = (TAPS == 2 && tap == 0) ? d : 0;
            const float* W = tap ? W1t : W0t;
            uint32_t aT = base + tap*16384u;
            uint32_t bT = base + (TAPS+tap)*16384u;
            #pragma unroll
            for (int i = 0; i < 4; i++) {
                int row = sm_row + i*32;       // 0..127
                int ch  = sm_ch;
                uint32_t dsw = (uint32_t)row*128 + (((uint32_t)ch ^ (row&7))<<4);
                // A
                int gm = row0 + row;
                int ok = (shift == 0) || ((gm & (Sn-1)) >= shift);
                const float* srcA = A + (size_t)(gm - shift)*Cn + kt + ch*4;
                CP16(aT + dsw, srcA, ok ? 16 : 0);
                // B
                const float* srcB = W + (size_t)(n0 + row)*Cn + kt + ch*4;
                CP16(bT + dsw, srcB, 16);
            }
        }
    };

    stage(0, 0);
    CPCOMMIT();

    for (int it = 0; it < 8; it++) {
        if (it < 7) {
            stage((it+1) & 1, (it+1)*32);
            CPCOMMIT();
            CPWAIT(1);
        } else {
            CPWAIT(0);
        }
        __syncthreads();
        uint32_t base = sb + (it & 1)*STAGE;
        #pragma unroll
        for (int tap = 0; tap < TAPS; tap++) {
            uint32_t aT = base + tap*16384u;
            uint32_t bT = base + (TAPS+tap)*16384u;
            #pragma unroll
            for (int ks = 0; ks < 32; ks += 8) {
                uint32_t x0 = (uint32_t)(ks << 2);
                uint32_t x1 = x0 + 16;
                uint32_t afr[4][4];
                #pragma unroll
                for (int mi = 0; mi < 4; mi++) {
                    afr[mi][0] = lds32(aT + (aRel[mi][0] ^ x0));
                    afr[mi][1] = lds32(aT + (aRel[mi][1] ^ x0));
                    afr[mi][2] = lds32(aT + (aRel[mi][0] ^ x1));
                    afr[mi][3] = lds32(aT + (aRel[mi][1] ^ x1));
                }
                uint32_t bfr[4][2];
                #pragma unroll
                for (int ni = 0; ni < 4; ni++) {
                    bfr[ni][0] = lds32(bT + (bRel[ni] ^ x0));
                    bfr[ni][1] = lds32(bT + (bRel[ni] ^ x1));
                }
                #pragma unroll
                for (int mi = 0; mi < 4; mi++)
                    #pragma unroll
                    for (int ni = 0; ni < 4; ni++)
                        mma_tf32(acc[mi][ni], afr[mi], bfr[ni]);
            }
        }
        __syncthreads();
    }

    // ---- epilogue
    #pragma unroll
    for (int mi = 0; mi < 4; mi++) {
        int r0g = row0 + m_base + mi*16 + g;
        #pragma unroll
        for (int ni = 0; ni < 4; ni++) {
            int c = n0 + n_base + ni*8 + tq*2;
            float bx = bias[c], by = bias[c+1];
            float2 o0 = make_float2(acc[mi][ni][0] + bx, acc[mi][ni][1] + by);
            float2 o1 = make_float2(acc[mi][ni][2] + bx, acc[mi][ni][3] + by);
            *(float2*)(out + (size_t)r0g*Cn + c)     = o0;
            *(float2*)(out + (size_t)(r0g+8)*Cn + c) = o1;
        }
    }
}

// ---------------------------------------------------------------------------
// Fused gate: E = A@We^T + be, G = A@Wg^T + bg, h += E*sigmoid(G)
// Tile 64x128x32, 8 warps (2x4), warp tile 32x32 per output.
__global__ __launch_bounds__(256) void gate_gemm_kernel(
    const float* __restrict__ A,
    const float* __restrict__ WeT, const float* __restrict__ WgT,
    const float* __restrict__ be, const float* __restrict__ bg,
    float* __restrict__ h)
{
    extern __shared__ char smem[];
    const uint32_t STAGE = 40960u;  // A 8KB + B0 16KB + B1 16KB
    uint32_t sb = smem_u32(smem);

    int tid = threadIdx.x;
    int wid = tid >> 5, lane = tid & 31;
    int g = lane >> 2, tq = lane & 3;
    int warp_m = wid >> 2, warp_n = wid & 3;
    int m_base = warp_m * 32, n_base = warp_n * 32;
    int row0 = blockIdx.x * 64, n0 = blockIdx.y * 128;

    float accE[2][4][4], accG[2][4][4];
    #pragma unroll
    for (int i = 0; i < 2; i++)
        #pragma unroll
        for (int j = 0; j < 4; j++)
            #pragma unroll
            for (int q = 0; q < 4; q++) { accE[i][j][q] = 0.f; accG[i][j][q] = 0.f; }

    uint32_t aRel[2][2], bRel[4];
    #pragma unroll
    for (int mi = 0; mi < 2; mi++) {
        int m = m_base + mi*16 + g;
        aRel[mi][0] = (uint32_t)m*128 + (g<<4) + tq*4;
        aRel[mi][1] = (uint32_t)(m+8)*128 + (g<<4) + tq*4;
    }
    #pragma unroll
    for (int ni = 0; ni < 4; ni++) {
        int n = n_base + ni*8 + g;
        bRel[ni] = (uint32_t)n*128 + (g<<4) + tq*4;
    }

    auto stage = [&](int buf, int kt) {
        uint32_t base = sb + buf*STAGE;
        // A: 64 rows x 8 chunks = 512
        #pragma unroll
        for (int i = 0; i < 2; i++) {
            int cidx = tid + 256*i;
            int row = cidx >> 3, ch = cidx & 7;
            uint32_t dsw = (uint32_t)row*128 + (((uint32_t)ch ^ (row&7))<<4);
            const float* src = A + (size_t)(row0 + row)*Cn + kt + ch*4;
            CP16(base + dsw, src, 16);
        }
        // B0/B1: 128 rows x 8 chunks each
        #pragma unroll
        for (int tap = 0; tap < 2; tap++) {
            const float* W = tap ? WgT : WeT;
            uint32_t bT = base + 8192u + tap*16384u;
            #pragma unroll
            for (int i = 0; i < 4; i++) {
                int cidx = tid + 256*i;
                int row = cidx >> 3, ch = cidx & 7;
                uint32_t dsw = (uint32_t)row*128 + (((uint32_t)ch ^ (row&7))<<4);
                const float* src = W + (size_t)(n0 + row)*Cn + kt + ch*4;
                CP16(bT + dsw, src, 16);
            }
        }
    };

    stage(0, 0);
    CPCOMMIT();

    for (int it = 0; it < 8; it++) {
        if (it < 7) {
            stage((it+1) & 1, (it+1)*32);
            CPCOMMIT();
            CPWAIT(1);
        } else {
            CPWAIT(0);
        }
        __syncthreads();
        uint32_t base = sb + (it & 1)*STAGE;
        uint32_t aT = base;
        uint32_t bTe = base + 8192u;
        uint32_t bTg = base + 8192u + 16384u;
        #pragma unroll
        for (int ks = 0; ks < 32; ks += 8) {
            uint32_t x0 = (uint32_t)(ks << 2);
            uint32_t x1 = x0 + 16;
            uint32_t afr[2][4];
            #pragma unroll
            for (int mi = 0; mi < 2; mi++) {
                afr[mi][0] = lds32(aT + (aRel[mi][0] ^ x0));
                afr[mi][1] = lds32(aT + (aRel[mi][1] ^ x0));
                afr[mi][2] = lds32(aT + (aRel[mi][0] ^ x1));
                afr[mi][3] = lds32(aT + (aRel[mi][1] ^ x1));
            }
            uint32_t be_[4][2], bg_[4][2];
            #pragma unroll
            for (int ni = 0; ni < 4; ni++) {
                be_[ni][0] = lds32(bTe + (bRel[ni] ^ x0));
                be_[ni][1] = lds32(bTe + (bRel[ni] ^ x1));
                bg_[ni][0] = lds32(bTg + (bRel[ni] ^ x0));
                bg_[ni][1] = lds32(bTg + (bRel[ni] ^ x1));
            }
            #pragma unroll
            for (int mi = 0; mi < 2; mi++)
                #pragma unroll
                for (int ni = 0; ni < 4; ni++) {
                    mma_tf32(accE[mi][ni], afr[mi], be_[ni]);
                    mma_tf32(accG[mi][ni], afr[mi], bg_[ni]);
                }
        }
        __syncthreads();
    }

    // ---- epilogue: h += E * sigmoid(G)
    #pragma unroll
    for (int mi = 0; mi < 2; mi++) {
        int r0g = row0 + m_base + mi*16 + g;
        #pragma unroll
        for (int ni = 0; ni < 4; ni++) {
            int c = n0 + n_base + ni*8 + tq*2;
            float bex = be[c], bey = be[c+1];
            float bgx = bg[c], bgy = bg[c+1];
            #pragma unroll
            for (int half = 0; half < 2; half++) {
                size_t r = (size_t)(r0g + half*8);
                float e0 = accE[mi][ni][half*2+0] + bex;
                float e1 = accE[mi][ni][half*2+1] + bey;
                float q0 = accG[mi][ni][half*2+0] + bgx;
                float q1 = accG[mi][ni][half*2+1] + bgy;
                float2 hv = *(float2*)(h + r*Cn + c);
                hv.x += e0 * (1.f/(1.f + __expf(-q0)));
                hv.y += e1 * (1.f/(1.f + __expf(-q1)));
                *(float2*)(h + r*Cn + c) = hv;
            }
        }
    }
}

// ---------------------------------------------------------------------------
__global__ __launch_bounds__(256) void latent_kernel(
    const float* __restrict__ z, const float* __restrict__ W,
    const float* __restrict__ bias)
{
    __shared__ float zs[Cn];
    int b = blockIdx.x, c = threadIdx.x;
    zs[c] = z[b*Cn + c];
    __syncthreads();
    float acc = bias[c];
    #pragma unroll 4
    for (int k = 0; k < Cn; k++) acc += zs[k] * W[k*Cn + c];
    g_lat[b*Cn + c] = acc;
}

__global__ __launch_bounds__(256) void embed_kernel(
    const int* __restrict__ x, const float* __restrict__ emb)
{
    int m = blockIdx.x*4 + (threadIdx.x >> 6);
    int t = threadIdx.x & 63;
    int b = m >> 9;
    int tok = x[m];
    float4 e = ((const float4*)(emb + (size_t)tok*Cn))[t];
    float4 l = ((const float4*)(g_lat + (size_t)b*Cn))[t];
    e.x += l.x; e.y += l.y; e.z += l.z; e.w += l.w;
    ((float4*)(g_h + (size_t)m*Cn))[t] = e;
}

__global__ __launch_bounds__(256) void ln_act_kernel(
    const float* __restrict__ in, float* __restrict__ out,
    const float* __restrict__ gamma, const float* __restrict__ beta)
{
    int warp = threadIdx.x >> 5, lane = threadIdx.x & 31;
    int m = blockIdx.x*8 + warp;
    const float4* ir = (const float4*)(in + (size_t)m*Cn);
    float4 v0 = ir[lane];
    float4 v1 = ir[lane + 32];
    float s = v0.x+v0.y+v0.z+v0.w + v1.x+v1.y+v1.z+v1.w;
    float q = v0.x*v0.x+v0.y*v0.y+v0.z*v0.z+v0.w*v0.w
            + v1.x*v1.x+v1.y*v1.y+v1.z*v1.z+v1.w*v1.w;
    #pragma unroll
    for (int o = 16; o; o >>= 1) {
        s += __shfl_xor_sync(0xffffffffu, s, o);
        q += __shfl_xor_sync(0xffffffffu, q, o);
    }
    float mu = s * (1.0f/Cn);
    float var = q * (1.0f/Cn) - mu*mu;
    float rs = rsqrtf(var + EPSn);
    int c0 = lane*4, c1 = 128 + lane*4;
    float4 ga = *(const float4*)(gamma + c0);
    float4 gb = *(const float4*)(gamma + c1);
    float4 ba = *(const float4*)(beta  + c0);
    float4 bb = *(const float4*)(beta  + c1);
    float4 o0, o1;
    #define LNA(xv, gg, bbv) ({ float y = (xv - mu)*rs*gg + bbv; y >= 0.f ? y : 0.01f*y; })
    o0.x = LNA(v0.x, ga.x, ba.x); o0.y = LNA(v0.y, ga.y, ba.y);
    o0.z = LNA(v0.z, ga.z, ba.z); o0.w = LNA(v0.w, ga.w, ba.w);
    o1.x = LNA(v1.x, gb.x, bb.x); o1.y = LNA(v1.y, gb.y, bb.y);
    o1.z = LNA(v1.z, gb.z, bb.z); o1.w = LNA(v1.w, gb.w, bb.w);
    #undef LNA
    float4* orow = (float4*)(out + (size_t)m*Cn);
    orow[lane]      = o0;
    orow[lane + 32] = o1;
}

__global__ __launch_bounds__(256) void head_kernel(
    const int* __restrict__ x, const float* __restrict__ outW,
    const float* __restrict__ outb, float* __restrict__ out)
{
    __shared__ float Ws[Cn][Vn+1];
    __shared__ float hs[8][Cn];
    int tid = threadIdx.x;
    for (int i = tid; i < Cn*Vn; i += 256)
        Ws[i >> 5][i & 31] = outW[i];
    int warp = tid >> 5, lane = tid & 31;
    int m = blockIdx.x*8 + warp;
    const float4* hr = (const float4*)(g_h + (size_t)m*Cn);
    ((float4*)hs[warp])[lane]      = hr[lane];
    ((float4*)hs[warp])[lane + 32] = hr[lane + 32];
    __syncthreads();
    float acc = outb[lane];
    #pragma unroll 8
    for (int k = 0; k < Cn; k++)
        acc += hs[warp][k] * Ws[k][lane];
    float mx = acc;
    #pragma unroll
    for (int o = 16; o; o >>= 1) mx = fmaxf(mx, __shfl_xor_sync(0xffffffffu, mx, o));
    float ex = expf(acc - mx), sum = ex;
    #pragma unroll
    for (int o = 16; o; o >>= 1) sum += __shfl_xor_sync(0xffffffffu, sum, o);
    float lse = mx + logf(sum);
    int b = m >> 9, s = m & (Sn-1);
    if (s < Sn-1) {
        int tgt = x[m + 1];
        float lt = __shfl_sync(0xffffffffu, acc, tgt);
        if (lane == 0) out[(size_t)b*(Sn-1) + s] = lt - lse;
    }
}

// ---------------------------------------------------------------------------
extern "C" void kernel_launch(void* const* d_in, const int* in_sizes, int n_in,
                              void* d_out, int out_size)
{
    const int*   x    = (const int*)  d_in[0];
    const float* z    = (const float*)d_in[1];
    const float* emb  = (const float*)d_in[2];
    const float* latW = (const float*)d_in[3];
    const float* latb = (const float*)d_in[4];
    const float* ln1g = (const float*)d_in[5];
    const float* ln1b = (const float*)d_in[6];
    const float* w1   = (const float*)d_in[7];
    const float* b1   = (const float*)d_in[8];
    const float* ln2g = (const float*)d_in[9];
    const float* ln2b = (const float*)d_in[10];
    const float* wd   = (const float*)d_in[11];
    const float* bd   = (const float*)d_in[12];
    const float* ln3g = (const float*)d_in[13];
    const float* ln3b = (const float*)d_in[14];
    const float* we   = (const float*)d_in[15];
    const float* be   = (const float*)d_in[16];
    const float* wg   = (const float*)d_in[17];
    const float* bg   = (const float*)d_in[18];
    const float* outW = (const float*)d_in[19];
    const float* outb = (const float*)d_in[20];

    float *hP, *aP, *tP, *wtP;
    cudaGetSymbolAddress((void**)&hP, g_h);
    cudaGetSymbolAddress((void**)&aP, g_a);
    cudaGetSymbolAddress((void**)&tP, g_t);
    cudaGetSymbolAddress((void**)&wtP, g_wt);

    const int SMEM1 = 65536;    // gemm_cp<1>: 2 stages x 32KB
    const int SMEM2 = 131072;   // gemm_cp<2>: 2 stages x 64KB
    const int SMEMG = 81920;    // gate: 2 stages x 40KB
    cudaFuncSetAttribute(gemm_cp_kernel<1>, cudaFuncAttributeMaxDynamicSharedMemorySize, SMEM1);
    cudaFuncSetAttribute(gemm_cp_kernel<2>, cudaFuncAttributeMaxDynamicSharedMemorySize, SMEM2);
    cudaFuncSetAttribute(gate_gemm_kernel,  cudaFuncAttributeMaxDynamicSharedMemorySize, SMEMG);

    dim3 tgrid(8, 8, 35);
    transpose_w_kernel<<<tgrid, 256>>>(w1, wd, we, wg);
    latent_kernel<<<Bn, Cn>>>(z, latW, latb);
    embed_kernel<<<Mn/4, 256>>>(x, emb);

    dim3 ggrid(Mn/128, 2);
    dim3 ggridG(Mn/64, 2);
    const size_t CC = (size_t)Cn*Cn;

    for (int i = 0; i < NLn; i++) {
        int d = 1 << i;
        ln_act_kernel<<<Mn/8, 256>>>(hP, aP, ln1g + i*Cn, ln1b + i*Cn);
        gemm_cp_kernel<1><<<ggrid, 256, SMEM1>>>(aP, wtP + (i*5+0)*CC, nullptr,
                                                 b1 + i*Cn, tP, 0);
        ln_act_kernel<<<Mn/8, 256>>>(tP, aP, ln2g + i*Cn, ln2b + i*Cn);
        gemm_cp_kernel<2><<<ggrid, 256, SMEM2>>>(aP, wtP + (i*5+1)*CC, wtP + (i*5+2)*CC,
                                                 bd + i*Cn, tP, d);
        ln_act_kernel<<<Mn/8, 256>>>(tP, aP, ln3g + i*Cn, ln3b + i*Cn);
        gate_gemm_kernel<<<ggridG, 256, SMEMG>>>(aP, wtP + (i*5+3)*CC, wtP + (i*5+4)*CC,
                                                 be + i*Cn, bg + i*Cn, hP);
    }

    head_kernel<<<Mn/8, 256>>>(x, outW, outb, (float*)d_out);
}

// round 6
// speedup vs baseline: 3.8383x; 1.1088x over previous
#include <cuda_runtime.h>
#include <cstdint>

// Problem dims
#define Bn   256
#define Sn   512
#define Cn   256
#define Vn   32
#define NLn  7
#define Mn   (Bn*Sn)
#define EPSn 1e-5f

// Scratch
__device__ float g_h[(size_t)Mn*Cn];
__device__ float g_a[(size_t)Mn*Cn];
__device__ float g_t[(size_t)Mn*Cn];
__device__ float g_lat[Bn*Cn];
__device__ float g_wt[35*65536];        // transposed weights [35][N=256][K=256]

// ---------------------------------------------------------------------------
__device__ __forceinline__ uint32_t smem_u32(const void* p) {
    uint32_t a;
    asm("{ .reg .u64 t; cvta.to.shared.u64 t, %1; cvt.u32.u64 %0, t; }"
        : "=r"(a) : "l"(p));
    return a;
}
__device__ __forceinline__ uint32_t lds32(uint32_t a) {
    uint32_t v;
    asm volatile("ld.shared.b32 %0, [%1];" : "=r"(v) : "r"(a));
    return v;
}
#define CP16(dst, src, sz) \
    asm volatile("cp.async.cg.shared.global [%0], [%1], 16, %2;" \
        :: "r"(dst), "l"(src), "r"(sz))
#define CPCOMMIT() asm volatile("cp.async.commit_group;")
#define CPWAIT(n)  asm volatile("cp.async.wait_group %0;" :: "n"(n))

__device__ __forceinline__ void mma_tf32(float* c, const uint32_t* a, const uint32_t* b) {
    asm volatile(
        "mma.sync.aligned.m16n8k8.row.col.f32.tf32.tf32.f32 "
        "{%0,%1,%2,%3}, {%4,%5,%6,%7}, {%8,%9}, {%0,%1,%2,%3};"
        : "+f"(c[0]), "+f"(c[1]), "+f"(c[2]), "+f"(c[3])
        : "r"(a[0]), "r"(a[1]), "r"(a[2]), "r"(a[3]), "r"(b[0]), "r"(b[1]));
}

// ---------------------------------------------------------------------------
// Weight transpose: g_wt[mat][n][k] = W[k][n]
__global__ __launch_bounds__(256) void transpose_w_kernel(
    const float* __restrict__ w1, const float* __restrict__ wd,
    const float* __restrict__ we, const float* __restrict__ wg)
{
    __shared__ float t[32][33];
    int mat = blockIdx.z;
    int layer = mat / 5, wh = mat % 5;
    const size_t CC = 65536;
    const float* src;
    if      (wh == 0) src = w1 + (size_t)layer*CC;
    else if (wh == 1) src = wd + (size_t)layer*2*CC;
    else if (wh == 2) src = wd + (size_t)layer*2*CC + CC;
    else if (wh == 3) src = we + (size_t)layer*CC;
    else              src = wg + (size_t)layer*CC;
    int tx = threadIdx.x & 31, ty = threadIdx.x >> 5;
    int k0 = blockIdx.x*32, n0 = blockIdx.y*32;
    #pragma unroll
    for (int j = 0; j < 32; j += 8)
        t[ty+j][tx] = src[(size_t)(k0+ty+j)*256 + n0 + tx];
    __syncthreads();
    float* dst = g_wt + (size_t)mat*CC;
    #pragma unroll
    for (int j = 0; j < 32; j += 8)
        dst[(size_t)(n0+ty+j)*256 + k0 + tx] = t[tx][ty+j];
}

// ---------------------------------------------------------------------------
// GEMM with fused LayerNorm+lrelu epilogue.
// Tile 64x256, BK=32, 8 warps (2 m x 4 n), warp tile 32x64.
// CONV=false: out = lrelu(ln(A@W0^T + bias))             (KITERS=8)
// CONV=true : out = lrelu(ln(shift_d(A)@W0^T + A@W1^T + bias)), K concat 512 (KITERS=16)
template<int KITERS, bool CONV>
__global__ __launch_bounds__(256, 2) void gemm_ln_kernel(
    const float* __restrict__ A,
    const float* __restrict__ W0t, const float* __restrict__ W1t,
    const float* __restrict__ bias,
    const float* __restrict__ gamma, const float* __restrict__ beta,
    float* __restrict__ out, int d)
{
    extern __shared__ char smem[];
    const uint32_t STAGE = 40960u;   // A 8KB + B 32KB
    uint32_t sb = smem_u32(smem);

    int tid = threadIdx.x;
    int wid = tid >> 5, lane = tid & 31;
    int g = lane >> 2, tq = lane & 3;
    int warp_m = wid >> 2, warp_n = wid & 3;
    int m_base = warp_m * 32, n_base = warp_n * 64;
    int row0 = blockIdx.x * 64;

    float acc[2][8][4];
    #pragma unroll
    for (int i = 0; i < 2; i++)
        #pragma unroll
        for (int j = 0; j < 8; j++)
            #pragma unroll
            for (int q = 0; q < 4; q++) acc[i][j][q] = 0.f;

    uint32_t aRel[2][2], bRel[8];
    #pragma unroll
    for (int mi = 0; mi < 2; mi++) {
        int m = m_base + mi*16 + g;
        aRel[mi][0] = (uint32_t)m*128 + (g<<4) + tq*4;
        aRel[mi][1] = (uint32_t)(m+8)*128 + (g<<4) + tq*4;
    }
    #pragma unroll
    for (int ni = 0; ni < 8; ni++) {
        int n = n_base + ni*8 + g;
        bRel[ni] = (uint32_t)n*128 + (g<<4) + tq*4;
    }

    auto stage = [&](int buf, int it) {
        int shift = (CONV && it < 8) ? d : 0;
        const float* W = (CONV && it >= 8) ? W1t : W0t;
        int kcol = (it & 7) * 32;
        uint32_t base = sb + buf*STAGE;
        // A: 64 rows x 8 chunks
        #pragma unroll
        for (int i = 0; i < 2; i++) {
            int cidx = tid + 256*i;
            int row = cidx >> 3, ch = cidx & 7;
            uint32_t dsw = (uint32_t)row*128 + (((uint32_t)ch ^ (row&7))<<4);
            int gm = row0 + row;
            int ok = (shift == 0) || ((gm & (Sn-1)) >= shift);
            const float* src = A + (size_t)(gm - shift)*Cn + kcol + ch*4;
            CP16(base + dsw, src, ok ? 16 : 0);
        }
        // B: 256 rows x 8 chunks
        #pragma unroll
        for (int i = 0; i < 8; i++) {
            int cidx = tid + 256*i;
            int row = cidx >> 3, ch = cidx & 7;
            uint32_t dsw = (uint32_t)row*128 + (((uint32_t)ch ^ (row&7))<<4);
            const float* src = W + (size_t)row*Cn + kcol + ch*4;
            CP16(base + 8192u + dsw, src, 16);
        }
    };

    stage(0, 0);
    CPCOMMIT();

    for (int it = 0; it < KITERS; it++) {
        if (it < KITERS-1) {
            stage((it+1) & 1, it+1);
            CPCOMMIT();
            CPWAIT(1);
        } else {
            CPWAIT(0);
        }
        __syncthreads();
        uint32_t base = sb + (it & 1)*STAGE;
        uint32_t aT = base, bT = base + 8192u;
        #pragma unroll
        for (int ks = 0; ks < 32; ks += 8) {
            uint32_t x0 = (uint32_t)(ks << 2);
            uint32_t x1 = x0 + 16;
            uint32_t afr[2][4];
            #pragma unroll
            for (int mi = 0; mi < 2; mi++) {
                afr[mi][0] = lds32(aT + (aRel[mi][0] ^ x0));
                afr[mi][1] = lds32(aT + (aRel[mi][1] ^ x0));
                afr[mi][2] = lds32(aT + (aRel[mi][0] ^ x1));
                afr[mi][3] = lds32(aT + (aRel[mi][1] ^ x1));
            }
            uint32_t bfr[8][2];
            #pragma unroll
            for (int ni = 0; ni < 8; ni++) {
                bfr[ni][0] = lds32(bT + (bRel[ni] ^ x0));
                bfr[ni][1] = lds32(bT + (bRel[ni] ^ x1));
            }
            #pragma unroll
            for (int mi = 0; mi < 2; mi++)
                #pragma unroll
                for (int ni = 0; ni < 8; ni++)
                    mma_tf32(acc[mi][ni], afr[mi], bfr[ni]);
        }
        __syncthreads();
    }

    // ---- epilogue: bias + row LayerNorm + lrelu
    // add bias, accumulate per-row sum/sumsq (rows: mi x half)
    float rsum[2][2] = {{0.f,0.f},{0.f,0.f}};
    float rsq [2][2] = {{0.f,0.f},{0.f,0.f}};
    #pragma unroll
    for (int mi = 0; mi < 2; mi++)
        #pragma unroll
        for (int ni = 0; ni < 8; ni++) {
            int c = n_base + ni*8 + tq*2;
            float bx = bias[c], by = bias[c+1];
            #pragma unroll
            for (int half = 0; half < 2; half++) {
                float v0 = acc[mi][ni][half*2+0] + bx;
                float v1 = acc[mi][ni][half*2+1] + by;
                acc[mi][ni][half*2+0] = v0;
                acc[mi][ni][half*2+1] = v1;
                rsum[mi][half] += v0 + v1;
                rsq [mi][half] += v0*v0 + v1*v1;
            }
        }
    // quad reduce (lanes sharing g hold the same rows)
    #pragma unroll
    for (int off = 1; off < 4; off <<= 1)
        #pragma unroll
        for (int mi = 0; mi < 2; mi++)
            #pragma unroll
            for (int half = 0; half < 2; half++) {
                rsum[mi][half] += __shfl_xor_sync(0xffffffffu, rsum[mi][half], off);
                rsq [mi][half] += __shfl_xor_sync(0xffffffffu, rsq [mi][half], off);
            }
    // cross-warp partials: red[row][warp_n]
    float2* red = (float2*)smem;   // 64 x 4 float2 = 2KB (smem free after last sync)
    if (tq == 0) {
        #pragma unroll
        for (int mi = 0; mi < 2; mi++)
            #pragma unroll
            for (int half = 0; half < 2; half++) {
                int r = m_base + mi*16 + half*8 + g;
                red[r*4 + warp_n] = make_float2(rsum[mi][half], rsq[mi][half]);
            }
    }
    __syncthreads();
    #pragma unroll
    for (int mi = 0; mi < 2; mi++)
        #pragma unroll
        for (int half = 0; half < 2; half++) {
            int r = m_base + mi*16 + half*8 + g;
            float2 p0 = red[r*4+0], p1 = red[r*4+1], p2 = red[r*4+2], p3 = red[r*4+3];
            float s = p0.x + p1.x + p2.x + p3.x;
            float q = p0.y + p1.y + p2.y + p3.y;
            float mu = s * (1.0f/Cn);
            float var = q * (1.0f/Cn) - mu*mu;
            float rs = rsqrtf(var + EPSn);
            size_t rowg = (size_t)(row0 + r);
            #pragma unroll
            for (int ni = 0; ni < 8; ni++) {
                int c = n_base + ni*8 + tq*2;
                float gx = gamma[c], gy = gamma[c+1];
                float bx = beta[c],  by = beta[c+1];
                float y0 = (acc[mi][ni][half*2+0] - mu)*rs*gx + bx;
                float y1 = (acc[mi][ni][half*2+1] - mu)*rs*gy + by;
                y0 = y0 >= 0.f ? y0 : 0.01f*y0;
                y1 = y1 >= 0.f ? y1 : 0.01f*y1;
                *(float2*)(out + rowg*Cn + c) = make_float2(y0, y1);
            }
        }
}

// ---------------------------------------------------------------------------
// Fused gate: E = A@We^T + be, G = A@Wg^T + bg, h += E*sigmoid(G)
// Tile 64x128x32, 8 warps (2x4), warp tile 32x32 per output.
__global__ __launch_bounds__(256) void gate_gemm_kernel(
    const float* __restrict__ A,
    const float* __restrict__ WeT, const float* __restrict__ WgT,
    const float* __restrict__ be, const float* __restrict__ bg,
    float* __restrict__ h)
{
    extern __shared__ char smem[];
    const uint32_t STAGE = 40960u;  // A 8KB + B0 16KB + B1 16KB
    uint32_t sb = smem_u32(smem);

    int tid = threadIdx.x;
    int wid = tid >> 5, lane = tid & 31;
    int g = lane >> 2, tq = lane & 3;
    int warp_m = wid >> 2, warp_n = wid & 3;
    int m_base = warp_m * 32, n_base = warp_n * 32;
    int row0 = blockIdx.x * 64, n0 = blockIdx.y * 128;

    float accE[2][4][4], accG[2][4][4];
    #pragma unroll
    for (int i = 0; i < 2; i++)
        #pragma unroll
        for (int j = 0; j < 4; j++)
            #pragma unroll
            for (int q = 0; q < 4; q++) { accE[i][j][q] = 0.f; accG[i][j][q] = 0.f; }

    uint32_t aRel[2][2], bRel[4];
    #pragma unroll
    for (int mi = 0; mi < 2; mi++) {
        int m = m_base + mi*16 + g;
        aRel[mi][0] = (uint32_t)m*128 + (g<<4) + tq*4;
        aRel[mi][1] = (uint32_t)(m+8)*128 + (g<<4) + tq*4;
    }
    #pragma unroll
    for (int ni = 0; ni < 4; ni++) {
        int n = n_base + ni*8 + g;
        bRel[ni] = (uint32_t)n*128 + (g<<4) + tq*4;
    }

    auto stage = [&](int buf, int kt) {
        uint32_t base = sb + buf*STAGE;
        #pragma unroll
        for (int i = 0; i < 2; i++) {
            int cidx = tid + 256*i;
            int row = cidx >> 3, ch = cidx & 7;
            uint32_t dsw = (uint32_t)row*128 + (((uint32_t)ch ^ (row&7))<<4);
            const float* src = A + (size_t)(row0 + row)*Cn + kt + ch*4;
            CP16(base + dsw, src, 16);
        }
        #pragma unroll
        for (int tap = 0; tap < 2; tap++) {
            const float* W = tap ? WgT : WeT;
            uint32_t bT = base + 8192u + tap*16384u;
            #pragma unroll
            for (int i = 0; i < 4; i++) {
                int cidx = tid + 256*i;
                int row = cidx >> 3, ch = cidx & 7;
                uint32_t dsw = (uint32_t)row*128 + (((uint32_t)ch ^ (row&7))<<4);
                const float* src = W + (size_t)(n0 + row)*Cn + kt + ch*4;
                CP16(bT + dsw, src, 16);
            }
        }
    };

    stage(0, 0);
    CPCOMMIT();

    for (int it = 0; it < 8; it++) {
        if (it < 7) {
            stage((it+1) & 1, (it+1)*32);
            CPCOMMIT();
            CPWAIT(1);
        } else {
            CPWAIT(0);
        }
        __syncthreads();
        uint32_t base = sb + (it & 1)*STAGE;
        uint32_t aT = base;
        uint32_t bTe = base + 8192u;
        uint32_t bTg = base + 8192u + 16384u;
        #pragma unroll
        for (int ks = 0; ks < 32; ks += 8) {
            uint32_t x0 = (uint32_t)(ks << 2);
            uint32_t x1 = x0 + 16;
            uint32_t afr[2][4];
            #pragma unroll
            for (int mi = 0; mi < 2; mi++) {
                afr[mi][0] = lds32(aT + (aRel[mi][0] ^ x0));
                afr[mi][1] = lds32(aT + (aRel[mi][1] ^ x0));
                afr[mi][2] = lds32(aT + (aRel[mi][0] ^ x1));
                afr[mi][3] = lds32(aT + (aRel[mi][1] ^ x1));
            }
            uint32_t be_[4][2], bg_[4][2];
            #pragma unroll
            for (int ni = 0; ni < 4; ni++) {
                be_[ni][0] = lds32(bTe + (bRel[ni] ^ x0));
                be_[ni][1] = lds32(bTe + (bRel[ni] ^ x1));
                bg_[ni][0] = lds32(bTg + (bRel[ni] ^ x0));
                bg_[ni][1] = lds32(bTg + (bRel[ni] ^ x1));
            }
            #pragma unroll
            for (int mi = 0; mi < 2; mi++)
                #pragma unroll
                for (int ni = 0; ni < 4; ni++) {
                    mma_tf32(accE[mi][ni], afr[mi], be_[ni]);
                    mma_tf32(accG[mi][ni], afr[mi], bg_[ni]);
                }
        }
        __syncthreads();
    }

    // ---- epilogue: h += E * sigmoid(G)
    #pragma unroll
    for (int mi = 0; mi < 2; mi++) {
        int r0g = row0 + m_base + mi*16 + g;
        #pragma unroll
        for (int ni = 0; ni < 4; ni++) {
            int c = n0 + n_base + ni*8 + tq*2;
            float bex = be[c], bey = be[c+1];
            float bgx = bg[c], bgy = bg[c+1];
            #pragma unroll
            for (int half = 0; half < 2; half++) {
                size_t r = (size_t)(r0g + half*8);
                float e0 = accE[mi][ni][half*2+0] + bex;
                float e1 = accE[mi][ni][half*2+1] + bey;
                float q0 = accG[mi][ni][half*2+0] + bgx;
                float q1 = accG[mi][ni][half*2+1] + bgy;
                float2 hv = *(float2*)(h + r*Cn + c);
                hv.x += e0 * (1.f/(1.f + __expf(-q0)));
                hv.y += e1 * (1.f/(1.f + __expf(-q1)));
                *(float2*)(h + r*Cn + c) = hv;
            }
        }
    }
}

// ---------------------------------------------------------------------------
__global__ __launch_bounds__(256) void latent_kernel(
    const float* __restrict__ z, const float* __restrict__ W,
    const float* __restrict__ bias)
{
    __shared__ float zs[Cn];
    int b = blockIdx.x, c = threadIdx.x;
    zs[c] = z[b*Cn + c];
    __syncthreads();
    float acc = bias[c];
    #pragma unroll 4
    for (int k = 0; k < Cn; k++) acc += zs[k] * W[k*Cn + c];
    g_lat[b*Cn + c] = acc;
}

__global__ __launch_bounds__(256) void embed_kernel(
    const int* __restrict__ x, const float* __restrict__ emb)
{
    int m = blockIdx.x*4 + (threadIdx.x >> 6);
    int t = threadIdx.x & 63;
    int b = m >> 9;
    int tok = x[m];
    float4 e = ((const float4*)(emb + (size_t)tok*Cn))[t];
    float4 l = ((const float4*)(g_lat + (size_t)b*Cn))[t];
    e.x += l.x; e.y += l.y; e.z += l.z; e.w += l.w;
    ((float4*)(g_h + (size_t)m*Cn))[t] = e;
}

__global__ __launch_bounds__(256) void ln_act_kernel(
    const float* __restrict__ in, float* __restrict__ out,
    const float* __restrict__ gamma, const float* __restrict__ beta)
{
    int warp = threadIdx.x >> 5, lane = threadIdx.x & 31;
    int m = blockIdx.x*8 + warp;
    const float4* ir = (const float4*)(in + (size_t)m*Cn);
    float4 v0 = ir[lane];
    float4 v1 = ir[lane + 32];
    float s = v0.x+v0.y+v0.z+v0.w + v1.x+v1.y+v1.z+v1.w;
    float q = v0.x*v0.x+v0.y*v0.y+v0.z*v0.z+v0.w*v0.w
            + v1.x*v1.x+v1.y*v1.y+v1.z*v1.z+v1.w*v1.w;
    #pragma unroll
    for (int o = 16; o; o >>= 1) {
        s += __shfl_xor_sync(0xffffffffu, s, o);
        q += __shfl_xor_sync(0xffffffffu, q, o);
    }
    float mu = s * (1.0f/Cn);
    float var = q * (1.0f/Cn) - mu*mu;
    float rs = rsqrtf(var + EPSn);
    int c0 = lane*4, c1 = 128 + lane*4;
    float4 ga = *(const float4*)(gamma + c0);
    float4 gb = *(const float4*)(gamma + c1);
    float4 ba = *(const float4*)(beta  + c0);
    float4 bb = *(const float4*)(beta  + c1);
    float4 o0, o1;
    #define LNA(xv, gg, bbv) ({ float y = (xv - mu)*rs*gg + bbv; y >= 0.f ? y : 0.01f*y; })
    o0.x = LNA(v0.x, ga.x, ba.x); o0.y = LNA(v0.y, ga.y, ba.y);
    o0.z = LNA(v0.z, ga.z, ba.z); o0.w = LNA(v0.w, ga.w, ba.w);
    o1.x = LNA(v1.x, gb.x, bb.x); o1.y = LNA(v1.y, gb.y, bb.y);
    o1.z = LNA(v1.z, gb.z, bb.z); o1.w = LNA(v1.w, gb.w, bb.w);
    #undef LNA
    float4* orow = (float4*)(out + (size_t)m*Cn);
    orow[lane]      = o0;
    orow[lane + 32] = o1;
}

__global__ __launch_bounds__(256) void head_kernel(
    const int* __restrict__ x, const float* __restrict__ outW,
    const float* __restrict__ outb, float* __restrict__ out)
{
    __shared__ float Ws[Cn][Vn+1];
    __shared__ float hs[8][Cn];
    int tid = threadIdx.x;
    for (int i = tid; i < Cn*Vn; i += 256)
        Ws[i >> 5][i & 31] = outW[i];
    int warp = tid >> 5, lane = tid & 31;
    int m = blockIdx.x*8 + warp;
    const float4* hr = (const float4*)(g_h + (size_t)m*Cn);
    ((float4*)hs[warp])[lane]      = hr[lane];
    ((float4*)hs[warp])[lane + 32] = hr[lane + 32];
    __syncthreads();
    float acc = outb[lane];
    #pragma unroll 8
    for (int k = 0; k < Cn; k++)
        acc += hs[warp][k] * Ws[k][lane];
    float mx = acc;
    #pragma unroll
    for (int o = 16; o; o >>= 1) mx = fmaxf(mx, __shfl_xor_sync(0xffffffffu, mx, o));
    float ex = expf(acc - mx), sum = ex;
    #pragma unroll
    for (int o = 16; o; o >>= 1) sum += __shfl_xor_sync(0xffffffffu, sum, o);
    float lse = mx + logf(sum);
    int b = m >> 9, s = m & (Sn-1);
    if (s < Sn-1) {
        int tgt = x[m + 1];
        float lt = __shfl_sync(0xffffffffu, acc, tgt);
        if (lane == 0) out[(size_t)b*(Sn-1) + s] = lt - lse;
    }
}

// ---------------------------------------------------------------------------
extern "C" void kernel_launch(void* const* d_in, const int* in_sizes, int n_in,
                              void* d_out, int out_size)
{
    const int*   x    = (const int*)  d_in[0];
    const float* z    = (const float*)d_in[1];
    const float* emb  = (const float*)d_in[2];
    const float* latW = (const float*)d_in[3];
    const float* latb = (const float*)d_in[4];
    const float* ln1g = (const float*)d_in[5];
    const float* ln1b = (const float*)d_in[6];
    const float* w1   = (const float*)d_in[7];
    const float* b1   = (const float*)d_in[8];
    const float* ln2g = (const float*)d_in[9];
    const float* ln2b = (const float*)d_in[10];
    const float* wd   = (const float*)d_in[11];
    const float* bd   = (const float*)d_in[12];
    const float* ln3g = (const float*)d_in[13];
    const float* ln3b = (const float*)d_in[14];
    const float* we   = (const float*)d_in[15];
    const float* be   = (const float*)d_in[16];
    const float* wg   = (const float*)d_in[17];
    const float* bg   = (const float*)d_in[18];
    const float* outW = (const float*)d_in[19];
    const float* outb = (const float*)d_in[20];

    float *hP, *aP, *tP, *wtP;
    cudaGetSymbolAddress((void**)&hP, g_h);
    cudaGetSymbolAddress((void**)&aP, g_a);
    cudaGetSymbolAddress((void**)&tP, g_t);
    cudaGetSymbolAddress((void**)&wtP, g_wt);

    const int SMEMLN = 81920;   // 2 stages x 40KB
    const int SMEMG  = 81920;
    cudaFuncSetAttribute(gemm_ln_kernel<8,false>,  cudaFuncAttributeMaxDynamicSharedMemorySize, SMEMLN);
    cudaFuncSetAttribute(gemm_ln_kernel<16,true>,  cudaFuncAttributeMaxDynamicSharedMemorySize, SMEMLN);
    cudaFuncSetAttribute(gate_gemm_kernel, cudaFuncAttributeMaxDynamicSharedMemorySize, SMEMG);

    dim3 tgrid(8, 8, 35);
    transpose_w_kernel<<<tgrid, 256>>>(w1, wd, we, wg);
    latent_kernel<<<Bn, Cn>>>(z, latW, latb);
    embed_kernel<<<Mn/4, 256>>>(x, emb);

    dim3 ggridG(Mn/64, 2);
    const size_t CC = (size_t)Cn*Cn;

    for (int i = 0; i < NLn; i++) {
        int d = 1 << i;
        // a = lrelu(ln1(h))
        ln_act_kernel<<<Mn/8, 256>>>(hP, aP, ln1g + i*Cn, ln1b + i*Cn);
        // t = lrelu(ln2(a @ w1 + b1))
        gemm_ln_kernel<8,false><<<Mn/64, 256, SMEMLN>>>(
            aP, wtP + (i*5+0)*CC, nullptr, b1 + i*Cn,
            ln2g + i*Cn, ln2b + i*Cn, tP, 0);
        // a = lrelu(ln3(shift(t,d) @ wd0 + t @ wd1 + bd))
        gemm_ln_kernel<16,true><<<Mn/64, 256, SMEMLN>>>(
            tP, wtP + (i*5+1)*CC, wtP + (i*5+2)*CC, bd + i*Cn,
            ln3g + i*Cn, ln3b + i*Cn, aP, d);
        // h += (a@we+be) * sigmoid(a@wg+bg)
        gate_gemm_kernel<<<ggridG, 256, SMEMG>>>(aP, wtP + (i*5+3)*CC, wtP + (i*5+4)*CC,
                                                 be + i*Cn, bg + i*Cn, hP);
    }

    head_kernel<<<Mn/8, 256>>>(x, outW, outb, (float*)d_out);
}